// round 2
// baseline (speedup 1.0000x reference)
#include <cuda_runtime.h>
#include <cuda_bf16.h>
#include <math.h>

#define N_NODES 50000
#define N_EDGES 800000
#define NB      250
#define NT      8
#define C_IN    32
#define C_OUT   64
#define NPG     200   // nodes per graph (contiguous)

// ---------------- scratch (static device globals; no allocation) -------------
__device__ float g_xc[NT * N_NODES * C_IN];   // transposed x: [t][n][c]
__device__ float g_agg[N_NODES * C_OUT];      // aggregation output
__device__ float g_h[N_NODES * C_OUT];        // layer activations
__device__ int   g_deg[N_NODES];
__device__ int   g_cnt[N_NODES];
__device__ int   g_rowptr[N_NODES + 1];
__device__ float g_dinv[N_NODES];
__device__ int   g_src[N_EDGES];
__device__ float g_norm[N_EDGES];

// ---------------- setup kernels ---------------------------------------------
__global__ void zero_setup_kernel() {
    int i = blockIdx.x * blockDim.x + threadIdx.x;
    if (i < N_NODES) { g_deg[i] = 0; g_cnt[i] = 0; }
}

__global__ void zero_out_kernel(float* out, int n) {
    int i = blockIdx.x * blockDim.x + threadIdx.x;
    if (i < n) out[i] = 0.f;
}

// x: [N, C_IN, T] -> g_xc: [T][N][C_IN]
__global__ void transpose_x_kernel(const float* __restrict__ x) {
    int i = blockIdx.x * blockDim.x + threadIdx.x;  // i = n*C_IN + c
    if (i >= N_NODES * C_IN) return;
    const float4* p = (const float4*)(x + (size_t)i * NT);
    float4 a = p[0], b4 = p[1];
    float v[8] = {a.x, a.y, a.z, a.w, b4.x, b4.y, b4.z, b4.w};
#pragma unroll
    for (int t = 0; t < NT; t++)
        g_xc[(size_t)t * (N_NODES * C_IN) + i] = v[t];
}

// edge_index delivered as int32 [2, E]
__global__ void count_deg_kernel(const int* __restrict__ ei) {
    int e = blockIdx.x * blockDim.x + threadIdx.x;
    if (e >= N_EDGES) return;
    int dst = ei[N_EDGES + e];
    if ((unsigned)dst < (unsigned)N_NODES)
        atomicAdd(&g_deg[dst], 1);
}

__global__ void dinv_kernel() {
    int n = blockIdx.x * blockDim.x + threadIdx.x;
    if (n >= N_NODES) return;
    g_dinv[n] = rsqrtf((float)(g_deg[n] + 1));  // +1 self loop
}

// single-block exclusive scan of g_deg -> g_rowptr
__global__ void scan_kernel() {
    __shared__ int wsum[32];
    int tid = threadIdx.x;        // 1024 threads
    int lane = tid & 31, wid = tid >> 5;
    int running = 0;
    for (int base = 0; base < N_NODES; base += 1024) {
        int i = base + tid;
        int v = (i < N_NODES) ? g_deg[i] : 0;
        int x = v;
#pragma unroll
        for (int off = 1; off < 32; off <<= 1) {
            int y = __shfl_up_sync(0xffffffffu, x, off);
            if (lane >= off) x += y;
        }
        if (lane == 31) wsum[wid] = x;
        __syncthreads();
        if (wid == 0) {
            int s = wsum[lane];
#pragma unroll
            for (int off = 1; off < 32; off <<= 1) {
                int y = __shfl_up_sync(0xffffffffu, s, off);
                if (lane >= off) s += y;
            }
            wsum[lane] = s;
        }
        __syncthreads();
        int woff = (wid > 0) ? wsum[wid - 1] : 0;
        int incl = x + woff;
        if (i < N_NODES) g_rowptr[i] = running + incl - v;
        int total = wsum[31];
        __syncthreads();
        running += total;
    }
    if (tid == 0) g_rowptr[N_NODES] = running;
}

__global__ void fill_csr_kernel(const int* __restrict__ ei) {
    int e = blockIdx.x * blockDim.x + threadIdx.x;
    if (e >= N_EDGES) return;
    int src = ei[e];
    int dst = ei[N_EDGES + e];
    if ((unsigned)src >= (unsigned)N_NODES ||
        (unsigned)dst >= (unsigned)N_NODES) return;
    int pos = g_rowptr[dst] + atomicAdd(&g_cnt[dst], 1);
    g_src[pos]  = src;
    g_norm[pos] = g_dinv[src] * g_dinv[dst];
}

// ---------------- aggregation: out[n] = dinv[n]^2*in[n] + sum_e norm*in[src] -
// warp per dst node; CH=32: lane->1 float; CH=64: lane->float2
__global__ void __launch_bounds__(256) agg32_kernel(const float* __restrict__ in,
                                                    float* __restrict__ out) {
    int w = (blockIdx.x * blockDim.x + threadIdx.x) >> 5;
    int lane = threadIdx.x & 31;
    if (w >= N_NODES) return;
    float dv = g_dinv[w];
    float acc = dv * dv * __ldg(&in[(size_t)w * 32 + lane]);
    int s = g_rowptr[w], e2 = g_rowptr[w + 1];
    for (int base = s; base < e2; base += 32) {
        int idx = base + lane;
        int sl = 0; float nl = 0.f;
        if (idx < e2) { sl = g_src[idx]; nl = g_norm[idx]; }
        int cnt = min(32, e2 - base);
        for (int j = 0; j < cnt; j++) {
            int src  = __shfl_sync(0xffffffffu, sl, j);
            float wt = __shfl_sync(0xffffffffu, nl, j);
            acc = fmaf(wt, __ldg(&in[(size_t)src * 32 + lane]), acc);
        }
    }
    out[(size_t)w * 32 + lane] = acc;
}

__global__ void __launch_bounds__(256) agg64_kernel(const float* __restrict__ in,
                                                    float* __restrict__ out) {
    int w = (blockIdx.x * blockDim.x + threadIdx.x) >> 5;
    int lane = threadIdx.x & 31;
    if (w >= N_NODES) return;
    const float2* in2 = (const float2*)in;
    float dv = g_dinv[w];
    float2 v0 = __ldg(&in2[(size_t)w * 32 + lane]);
    float ax = dv * dv * v0.x, ay = dv * dv * v0.y;
    int s = g_rowptr[w], e2 = g_rowptr[w + 1];
    for (int base = s; base < e2; base += 32) {
        int idx = base + lane;
        int sl = 0; float nl = 0.f;
        if (idx < e2) { sl = g_src[idx]; nl = g_norm[idx]; }
        int cnt = min(32, e2 - base);
        for (int j = 0; j < cnt; j++) {
            int src  = __shfl_sync(0xffffffffu, sl, j);
            float wt = __shfl_sync(0xffffffffu, nl, j);
            float2 v = __ldg(&in2[(size_t)src * 32 + lane]);
            ax = fmaf(wt, v.x, ax);
            ay = fmaf(wt, v.y, ay);
        }
    }
    float2 o; o.x = ax; o.y = ay;
    ((float2*)out)[(size_t)w * 32 + lane] = o;
}

// ---------------- GEMM: out = relu(in[N,CIN] @ W[CIN,64] + b) ----------------
// 64-node x 64-col tile per block, 4x4 register micro-tile per thread.
template <int CIN>
__global__ void __launch_bounds__(256) gemm_bias_relu_kernel(
    const float* __restrict__ in, const float* __restrict__ W,
    const float* __restrict__ bias, float* __restrict__ out) {
    __shared__ __align__(16) float Wsm[CIN * 64];
    __shared__ __align__(16) float rsm[CIN * 68];  // [k][node], stride 68 (pad)
    __shared__ __align__(16) float bsm[64];
    int tid = threadIdx.x;
    int n0 = blockIdx.x * 64;

    for (int i = tid; i < CIN * 64; i += 256) Wsm[i] = W[i];
    if (tid < 64) bsm[tid] = bias[tid];
    for (int i = tid; i < 64 * CIN; i += 256) {
        int k = i % CIN, n = i / CIN;
        int node = n0 + n;
        rsm[k * 68 + n] = (node < N_NODES) ? in[(size_t)node * CIN + k] : 0.f;
    }
    __syncthreads();

    int cg = tid & 15;   // col group -> cols cg*4..+3
    int nq = tid >> 4;   // node quad -> nodes nq*4..+3
    float acc[4][4];
#pragma unroll
    for (int i = 0; i < 4; i++)
#pragma unroll
        for (int j = 0; j < 4; j++) acc[i][j] = 0.f;

#pragma unroll
    for (int k = 0; k < CIN; k++) {
        float4 r = *(const float4*)(rsm + k * 68 + nq * 4);
        float4 w = *(const float4*)(Wsm + k * 64 + cg * 4);
        acc[0][0] = fmaf(r.x, w.x, acc[0][0]); acc[0][1] = fmaf(r.x, w.y, acc[0][1]);
        acc[0][2] = fmaf(r.x, w.z, acc[0][2]); acc[0][3] = fmaf(r.x, w.w, acc[0][3]);
        acc[1][0] = fmaf(r.y, w.x, acc[1][0]); acc[1][1] = fmaf(r.y, w.y, acc[1][1]);
        acc[1][2] = fmaf(r.y, w.z, acc[1][2]); acc[1][3] = fmaf(r.y, w.w, acc[1][3]);
        acc[2][0] = fmaf(r.z, w.x, acc[2][0]); acc[2][1] = fmaf(r.z, w.y, acc[2][1]);
        acc[2][2] = fmaf(r.z, w.z, acc[2][2]); acc[2][3] = fmaf(r.z, w.w, acc[2][3]);
        acc[3][0] = fmaf(r.w, w.x, acc[3][0]); acc[3][1] = fmaf(r.w, w.y, acc[3][1]);
        acc[3][2] = fmaf(r.w, w.z, acc[3][2]); acc[3][3] = fmaf(r.w, w.w, acc[3][3]);
    }

    float4 bv = *(const float4*)(bsm + cg * 4);
#pragma unroll
    for (int i = 0; i < 4; i++) {
        int node = n0 + nq * 4 + i;
        if (node < N_NODES) {
            float4 o;
            o.x = fmaxf(acc[i][0] + bv.x, 0.f);
            o.y = fmaxf(acc[i][1] + bv.y, 0.f);
            o.z = fmaxf(acc[i][2] + bv.z, 0.f);
            o.w = fmaxf(acc[i][3] + bv.w, 0.f);
            *(float4*)(out + (size_t)node * 64 + cg * 4) = o;
        }
    }
}

// ---------------- pooling: out[b, 0:64, t] += max, out[b, 64:128, t] += mean -
__global__ void __launch_bounds__(256) pool_kernel(const float* __restrict__ h,
                                                   float* __restrict__ out, int t) {
    int b = blockIdx.x;
    int tid = threadIdx.x;
    int c = tid & 63, g = tid >> 6;  // 4 groups
    const float* hp = h + (size_t)b * NPG * 64;
    float mx = -1e30f, sm = 0.f;
    for (int i = g; i < NPG; i += 4) {
        float v = hp[(size_t)i * 64 + c];
        mx = fmaxf(mx, v);
        sm += v;
    }
    __shared__ float smx[4][64], ssm[4][64];
    smx[g][c] = mx; ssm[g][c] = sm;
    __syncthreads();
    if (tid < 64) {
        float m = fmaxf(fmaxf(smx[0][tid], smx[1][tid]),
                        fmaxf(smx[2][tid], smx[3][tid]));
        float s = ssm[0][tid] + ssm[1][tid] + ssm[2][tid] + ssm[3][tid];
        out[b * 1024 + tid * 8 + t]        += m;
        out[b * 1024 + (64 + tid) * 8 + t] += s * (1.f / (float)NPG);
    }
}

// ---------------- launch -----------------------------------------------------
extern "C" void kernel_launch(void* const* d_in, const int* in_sizes, int n_in,
                              void* d_out, int out_size) {
    const float* x  = (const float*)d_in[0];
    const int*   ei = (const int*)d_in[1];     // int32 [2, E]
    // d_in[2] = batch (structure is known: 200 contiguous nodes per graph)
    const float* W1 = (const float*)d_in[3];
    const float* b1 = (const float*)d_in[4];
    const float* W2 = (const float*)d_in[5];
    const float* b2 = (const float*)d_in[6];
    const float* W3 = (const float*)d_in[7];
    const float* b3 = (const float*)d_in[8];
    float* out = (float*)d_out;

    float *xc, *agg, *h;
    cudaGetSymbolAddress((void**)&xc,  g_xc);
    cudaGetSymbolAddress((void**)&agg, g_agg);
    cudaGetSymbolAddress((void**)&h,   g_h);

    // setup
    zero_setup_kernel<<<(N_NODES + 255) / 256, 256>>>();
    zero_out_kernel<<<(NB * 128 * NT + 255) / 256, 256>>>(out, NB * 128 * NT);
    transpose_x_kernel<<<(N_NODES * C_IN + 255) / 256, 256>>>(x);
    count_deg_kernel<<<(N_EDGES + 255) / 256, 256>>>(ei);
    dinv_kernel<<<(N_NODES + 255) / 256, 256>>>();
    scan_kernel<<<1, 1024>>>();
    fill_csr_kernel<<<(N_EDGES + 255) / 256, 256>>>(ei);

    const int AGG_GRID  = N_NODES / 8;              // 8 warps/block
    const int GEMM_GRID = (N_NODES + 63) / 64;

    for (int t = 0; t < NT; t++) {
        const float* xt = xc + (size_t)t * N_NODES * C_IN;
        // layer 1: agg(x_t) [N,32] -> gemm W1 -> h1
        agg32_kernel<<<AGG_GRID, 256>>>(xt, agg);
        gemm_bias_relu_kernel<32><<<GEMM_GRID, 256>>>(agg, W1, b1, h);
        pool_kernel<<<NB, 256>>>(h, out, t);
        // layer 2
        agg64_kernel<<<AGG_GRID, 256>>>(h, agg);
        gemm_bias_relu_kernel<64><<<GEMM_GRID, 256>>>(agg, W2, b2, h);
        pool_kernel<<<NB, 256>>>(h, out, t);
        // layer 3
        agg64_kernel<<<AGG_GRID, 256>>>(h, agg);
        gemm_bias_relu_kernel<64><<<GEMM_GRID, 256>>>(agg, W3, b3, h);
        pool_kernel<<<NB, 256>>>(h, out, t);
    }
}

// round 3
// speedup vs baseline: 1.4182x; 1.4182x over previous
#include <cuda_runtime.h>
#include <cuda_fp16.h>
#include <math.h>

#define N_NODES 50000
#define N_EDGES 800000
#define NB      250
#define NT      8
#define C_IN    32
#define C_OUT   64
#define NPG     200   // nodes per graph (contiguous)

// ---------------- scratch (static device globals; no allocation) -------------
__device__ __half g_xh[(size_t)N_NODES * NT * C_IN];          // [n][t][c] fp16
__device__ __half g_h[(size_t)NT * N_NODES * C_OUT];          // [t][n][c] fp16
__device__ float  g_agg[(size_t)NT * N_NODES * C_OUT];        // [t][n][c] fp32
__device__ int    g_deg[N_NODES];
__device__ int    g_cnt[N_NODES];
__device__ int    g_rowptr[N_NODES + 1];
__device__ float  g_dinv[N_NODES];
__device__ int    g_src[N_EDGES];
__device__ float  g_norm[N_EDGES];

// ---------------- setup kernels ---------------------------------------------
__global__ void zero_setup_kernel() {
    int i = blockIdx.x * blockDim.x + threadIdx.x;
    if (i < N_NODES) { g_deg[i] = 0; g_cnt[i] = 0; }
}

__global__ void zero_out_kernel(float* out, int n) {
    int i = blockIdx.x * blockDim.x + threadIdx.x;
    if (i < n) out[i] = 0.f;
}

// x: [N, C_IN, T] fp32 -> g_xh: [n][t][c] fp16
__global__ void transpose_x_kernel(const float* __restrict__ x) {
    int i = blockIdx.x * blockDim.x + threadIdx.x;  // i = n*C_IN + c
    if (i >= N_NODES * C_IN) return;
    int n = i / C_IN, c = i % C_IN;
    const float4* p = (const float4*)(x + (size_t)i * NT);
    float4 a = p[0], b4 = p[1];
    float v[8] = {a.x, a.y, a.z, a.w, b4.x, b4.y, b4.z, b4.w};
#pragma unroll
    for (int t = 0; t < NT; t++)
        g_xh[(size_t)n * (NT * C_IN) + t * C_IN + c] = __float2half_rn(v[t]);
}

__global__ void count_deg_kernel(const int* __restrict__ ei) {
    int e = blockIdx.x * blockDim.x + threadIdx.x;
    if (e >= N_EDGES) return;
    int dst = ei[N_EDGES + e];
    if ((unsigned)dst < (unsigned)N_NODES)
        atomicAdd(&g_deg[dst], 1);
}

__global__ void dinv_kernel() {
    int n = blockIdx.x * blockDim.x + threadIdx.x;
    if (n >= N_NODES) return;
    g_dinv[n] = rsqrtf((float)(g_deg[n] + 1));  // +1 self loop
}

// single-block exclusive scan of g_deg -> g_rowptr
__global__ void scan_kernel() {
    __shared__ int wsum[32];
    int tid = threadIdx.x;        // 1024 threads
    int lane = tid & 31, wid = tid >> 5;
    int running = 0;
    for (int base = 0; base < N_NODES; base += 1024) {
        int i = base + tid;
        int v = (i < N_NODES) ? g_deg[i] : 0;
        int x = v;
#pragma unroll
        for (int off = 1; off < 32; off <<= 1) {
            int y = __shfl_up_sync(0xffffffffu, x, off);
            if (lane >= off) x += y;
        }
        if (lane == 31) wsum[wid] = x;
        __syncthreads();
        if (wid == 0) {
            int s = wsum[lane];
#pragma unroll
            for (int off = 1; off < 32; off <<= 1) {
                int y = __shfl_up_sync(0xffffffffu, s, off);
                if (lane >= off) s += y;
            }
            wsum[lane] = s;
        }
        __syncthreads();
        int woff = (wid > 0) ? wsum[wid - 1] : 0;
        int incl = x + woff;
        if (i < N_NODES) g_rowptr[i] = running + incl - v;
        int total = wsum[31];
        __syncthreads();
        running += total;
    }
    if (tid == 0) g_rowptr[N_NODES] = running;
}

__global__ void fill_csr_kernel(const int* __restrict__ ei) {
    int e = blockIdx.x * blockDim.x + threadIdx.x;
    if (e >= N_EDGES) return;
    int src = ei[e];
    int dst = ei[N_EDGES + e];
    if ((unsigned)src >= (unsigned)N_NODES ||
        (unsigned)dst >= (unsigned)N_NODES) return;
    int pos = g_rowptr[dst] + atomicAdd(&g_cnt[dst], 1);
    g_src[pos]  = src;
    g_norm[pos] = g_dinv[src] * g_dinv[dst];
}

// ---------------- aggregation (all t at once) --------------------------------
// agg32: warp per dst node; 4 passes of t-pairs packed in the lane dimension.
// g_xh viewed as half2: node row = 128 half2; pass p covers t={2p,2p+1}:
//   lane l -> t = 2p + (l>>4), c = (l&15)*2  == half2 index n*128 + 32p + l
__global__ void __launch_bounds__(256) agg32_all_kernel(float* __restrict__ out) {
    int w = (blockIdx.x * blockDim.x + threadIdx.x) >> 5;
    int lane = threadIdx.x & 31;
    if (w >= N_NODES) return;
    const __half2* X = (const __half2*)g_xh;
    float dv = g_dinv[w];
    float dv2 = dv * dv;
    float2 acc[4];
#pragma unroll
    for (int p = 0; p < 4; p++) {
        float2 f = __half22float2(X[(size_t)w * 128 + p * 32 + lane]);
        acc[p].x = dv2 * f.x; acc[p].y = dv2 * f.y;
    }
    int s = g_rowptr[w], e2 = g_rowptr[w + 1];
    for (int base = s; base < e2; base += 32) {
        int idx = base + lane;
        int sl = 0; float nl = 0.f;
        if (idx < e2) { sl = g_src[idx]; nl = g_norm[idx]; }
        int cnt = min(32, e2 - base);
        for (int j = 0; j < cnt; j++) {
            int src  = __shfl_sync(0xffffffffu, sl, j);
            float wt = __shfl_sync(0xffffffffu, nl, j);
#pragma unroll
            for (int p = 0; p < 4; p++) {
                float2 f = __half22float2(X[(size_t)src * 128 + p * 32 + lane]);
                acc[p].x = fmaf(wt, f.x, acc[p].x);
                acc[p].y = fmaf(wt, f.y, acc[p].y);
            }
        }
    }
    float2* o2 = (float2*)out;
#pragma unroll
    for (int p = 0; p < 4; p++) {
        int t = 2 * p + (lane >> 4);
        int cpair = lane & 15;
        o2[(size_t)t * N_NODES * 16 + (size_t)w * 16 + cpair] = acc[p];
    }
}

// agg64: warp per dst node; lane -> half2 channel pair; loop all 8 t inside.
__global__ void __launch_bounds__(256) agg64_all_kernel(const __half* __restrict__ hin,
                                                        float* __restrict__ out) {
    int w = (blockIdx.x * blockDim.x + threadIdx.x) >> 5;
    int lane = threadIdx.x & 31;
    if (w >= N_NODES) return;
    const __half2* H = (const __half2*)hin;
    float dv = g_dinv[w];
    float dv2 = dv * dv;
    float2 acc[NT];
#pragma unroll
    for (int t = 0; t < NT; t++) {
        float2 f = __half22float2(H[(size_t)t * N_NODES * 32 + (size_t)w * 32 + lane]);
        acc[t].x = dv2 * f.x; acc[t].y = dv2 * f.y;
    }
    int s = g_rowptr[w], e2 = g_rowptr[w + 1];
    for (int base = s; base < e2; base += 32) {
        int idx = base + lane;
        int sl = 0; float nl = 0.f;
        if (idx < e2) { sl = g_src[idx]; nl = g_norm[idx]; }
        int cnt = min(32, e2 - base);
        for (int j = 0; j < cnt; j++) {
            int src  = __shfl_sync(0xffffffffu, sl, j);
            float wt = __shfl_sync(0xffffffffu, nl, j);
#pragma unroll
            for (int t = 0; t < NT; t++) {
                float2 f = __half22float2(H[(size_t)t * N_NODES * 32 + (size_t)src * 32 + lane]);
                acc[t].x = fmaf(wt, f.x, acc[t].x);
                acc[t].y = fmaf(wt, f.y, acc[t].y);
            }
        }
    }
    float2* o2 = (float2*)out;
#pragma unroll
    for (int t = 0; t < NT; t++)
        o2[(size_t)t * N_NODES * 32 + (size_t)w * 32 + lane] = acc[t];
}

// ---------------- GEMM: h = relu(agg[8N,CIN] @ W[CIN,64] + b), fp16 out ------
// 64-node x 64-col tile per block, 4x4 register micro-tile; grid.y = t.
template <int CIN>
__global__ void __launch_bounds__(256) gemm_bias_relu_kernel(
    const float* __restrict__ in, const float* __restrict__ W,
    const float* __restrict__ bias, __half* __restrict__ out) {
    __shared__ __align__(16) float Wsm[CIN * 64];
    __shared__ __align__(16) float rsm[CIN * 68];  // [k][node], stride 68 (pad)
    __shared__ __align__(16) float bsm[64];
    int tid = threadIdx.x;
    int n0 = blockIdx.x * 64;
    const float* inT = in + (size_t)blockIdx.y * N_NODES * CIN;
    __half* outT = out + (size_t)blockIdx.y * N_NODES * 64;

    for (int i = tid; i < CIN * 64; i += 256) Wsm[i] = W[i];
    if (tid < 64) bsm[tid] = bias[tid];
    for (int i = tid; i < 64 * CIN; i += 256) {
        int k = i % CIN, n = i / CIN;
        int node = n0 + n;
        rsm[k * 68 + n] = (node < N_NODES) ? inT[(size_t)node * CIN + k] : 0.f;
    }
    __syncthreads();

    int cg = tid & 15;   // col group -> cols cg*4..+3
    int nq = tid >> 4;   // node quad -> nodes nq*4..+3
    float acc[4][4];
#pragma unroll
    for (int i = 0; i < 4; i++)
#pragma unroll
        for (int j = 0; j < 4; j++) acc[i][j] = 0.f;

#pragma unroll
    for (int k = 0; k < CIN; k++) {
        float4 r = *(const float4*)(rsm + k * 68 + nq * 4);
        float4 w = *(const float4*)(Wsm + k * 64 + cg * 4);
        acc[0][0] = fmaf(r.x, w.x, acc[0][0]); acc[0][1] = fmaf(r.x, w.y, acc[0][1]);
        acc[0][2] = fmaf(r.x, w.z, acc[0][2]); acc[0][3] = fmaf(r.x, w.w, acc[0][3]);
        acc[1][0] = fmaf(r.y, w.x, acc[1][0]); acc[1][1] = fmaf(r.y, w.y, acc[1][1]);
        acc[1][2] = fmaf(r.y, w.z, acc[1][2]); acc[1][3] = fmaf(r.y, w.w, acc[1][3]);
        acc[2][0] = fmaf(r.z, w.x, acc[2][0]); acc[2][1] = fmaf(r.z, w.y, acc[2][1]);
        acc[2][2] = fmaf(r.z, w.z, acc[2][2]); acc[2][3] = fmaf(r.z, w.w, acc[2][3]);
        acc[3][0] = fmaf(r.w, w.x, acc[3][0]); acc[3][1] = fmaf(r.w, w.y, acc[3][1]);
        acc[3][2] = fmaf(r.w, w.z, acc[3][2]); acc[3][3] = fmaf(r.w, w.w, acc[3][3]);
    }

    float4 bv = *(const float4*)(bsm + cg * 4);
#pragma unroll
    for (int i = 0; i < 4; i++) {
        int node = n0 + nq * 4 + i;
        if (node < N_NODES) {
            float ox = fmaxf(acc[i][0] + bv.x, 0.f);
            float oy = fmaxf(acc[i][1] + bv.y, 0.f);
            float oz = fmaxf(acc[i][2] + bv.z, 0.f);
            float ow = fmaxf(acc[i][3] + bv.w, 0.f);
            __half2* dst = (__half2*)(outT + (size_t)node * 64 + cg * 4);
            dst[0] = __floats2half2_rn(ox, oy);
            dst[1] = __floats2half2_rn(oz, ow);
        }
    }
}

// ---------------- pooling (all t): out[b, 0:64, t] += max, [64:128] += mean --
__global__ void __launch_bounds__(256) pool_all_kernel(const __half* __restrict__ h,
                                                       float* __restrict__ out) {
    int b = blockIdx.x, t = blockIdx.y;
    int tid = threadIdx.x;
    int c = tid & 63, g = tid >> 6;  // 4 groups
    const __half* hp = h + (size_t)t * N_NODES * 64 + (size_t)b * NPG * 64;
    float mx = -1e30f, sm = 0.f;
    for (int i = g; i < NPG; i += 4) {
        float v = __half2float(hp[(size_t)i * 64 + c]);
        mx = fmaxf(mx, v);
        sm += v;
    }
    __shared__ float smx[4][64], ssm[4][64];
    smx[g][c] = mx; ssm[g][c] = sm;
    __syncthreads();
    if (tid < 64) {
        float m = fmaxf(fmaxf(smx[0][tid], smx[1][tid]),
                        fmaxf(smx[2][tid], smx[3][tid]));
        float s = ssm[0][tid] + ssm[1][tid] + ssm[2][tid] + ssm[3][tid];
        out[b * 1024 + tid * 8 + t]        += m;
        out[b * 1024 + (64 + tid) * 8 + t] += s * (1.f / (float)NPG);
    }
}

// ---------------- launch -----------------------------------------------------
extern "C" void kernel_launch(void* const* d_in, const int* in_sizes, int n_in,
                              void* d_out, int out_size) {
    const float* x  = (const float*)d_in[0];
    const int*   ei = (const int*)d_in[1];     // int32 [2, E]
    // d_in[2] = batch (structure known: 200 contiguous nodes per graph)
    const float* W1 = (const float*)d_in[3];
    const float* b1 = (const float*)d_in[4];
    const float* W2 = (const float*)d_in[5];
    const float* b2 = (const float*)d_in[6];
    const float* W3 = (const float*)d_in[7];
    const float* b3 = (const float*)d_in[8];
    float* out = (float*)d_out;

    float *agg; __half *h;
    cudaGetSymbolAddress((void**)&agg, g_agg);
    cudaGetSymbolAddress((void**)&h,   g_h);

    // setup
    zero_setup_kernel<<<(N_NODES + 255) / 256, 256>>>();
    zero_out_kernel<<<(NB * 128 * NT + 255) / 256, 256>>>(out, NB * 128 * NT);
    transpose_x_kernel<<<(N_NODES * C_IN + 255) / 256, 256>>>(x);
    count_deg_kernel<<<(N_EDGES + 255) / 256, 256>>>(ei);
    dinv_kernel<<<(N_NODES + 255) / 256, 256>>>();
    scan_kernel<<<1, 1024>>>();
    fill_csr_kernel<<<(N_EDGES + 255) / 256, 256>>>(ei);

    const int AGG_GRID = N_NODES / 8;                 // 8 warps/block, warp=node
    dim3 gemm_grid((N_NODES + 63) / 64, NT);
    dim3 pool_grid(NB, NT);

    // layer 1 (all t)
    agg32_all_kernel<<<AGG_GRID, 256>>>(agg);
    gemm_bias_relu_kernel<32><<<gemm_grid, 256>>>(agg, W1, b1, h);
    pool_all_kernel<<<pool_grid, 256>>>(h, out);
    // layer 2 (all t)
    agg64_all_kernel<<<AGG_GRID, 256>>>(h, agg);
    gemm_bias_relu_kernel<64><<<gemm_grid, 256>>>(agg, W2, b2, h);
    pool_all_kernel<<<pool_grid, 256>>>(h, out);
    // layer 3 (all t)
    agg64_all_kernel<<<AGG_GRID, 256>>>(h, agg);
    gemm_bias_relu_kernel<64><<<gemm_grid, 256>>>(agg, W3, b3, h);
    pool_all_kernel<<<pool_grid, 256>>>(h, out);
}

// round 5
// speedup vs baseline: 2.4386x; 1.7195x over previous
#include <cuda_runtime.h>
#include <cuda_fp16.h>
#include <math.h>
#include <stdint.h>

#define N_NODES 50000
#define N_EDGES 800000
#define NB      250
#define NT      8
#define C_IN    32
#define C_OUT   64
#define NPG     200   // nodes per graph (contiguous)
#define M_ALL   (NT * N_NODES)   // 400000 rows, divisible by 128

// ---------------- scratch (static device globals; no allocation) -------------
__device__ __half g_xh[(size_t)N_NODES * NT * C_IN];    // [n][t][c] fp16
__device__ __half g_h[(size_t)NT * N_NODES * C_OUT];    // [t][n][c] fp16
__device__ __half g_agg[(size_t)NT * N_NODES * C_OUT];  // [t][n][c] fp16
__device__ __half g_W1h[C_IN * C_OUT];
__device__ __half g_W2h[C_OUT * C_OUT];
__device__ __half g_W3h[C_OUT * C_OUT];
__device__ int    g_deg[N_NODES];
__device__ int    g_cnt[N_NODES];
__device__ int    g_rowptr[N_NODES + 1];
__device__ float  g_dinv[N_NODES];
__device__ int    g_src[N_EDGES];
__device__ float  g_norm[N_EDGES];

// ---------------- setup kernels ---------------------------------------------
__global__ void zero_setup_kernel() {
    int i = blockIdx.x * blockDim.x + threadIdx.x;
    if (i < N_NODES) { g_deg[i] = 0; g_cnt[i] = 0; }
}

__global__ void zero_out_kernel(float* out, int n) {
    int i = blockIdx.x * blockDim.x + threadIdx.x;
    if (i < n) out[i] = 0.f;
}

__global__ void convert_w_kernel(const float* __restrict__ W1,
                                 const float* __restrict__ W2,
                                 const float* __restrict__ W3) {
    int i = blockIdx.x * blockDim.x + threadIdx.x;
    if (i < C_IN * C_OUT)  g_W1h[i] = __float2half_rn(W1[i]);
    if (i < C_OUT * C_OUT) { g_W2h[i] = __float2half_rn(W2[i]);
                             g_W3h[i] = __float2half_rn(W3[i]); }
}

// x: [N, C_IN, T] fp32 -> g_xh: [n][t][c] fp16
__global__ void transpose_x_kernel(const float* __restrict__ x) {
    int i = blockIdx.x * blockDim.x + threadIdx.x;  // i = n*C_IN + c
    if (i >= N_NODES * C_IN) return;
    int n = i / C_IN, c = i % C_IN;
    const float4* p = (const float4*)(x + (size_t)i * NT);
    float4 a = p[0], b4 = p[1];
    float v[8] = {a.x, a.y, a.z, a.w, b4.x, b4.y, b4.z, b4.w};
#pragma unroll
    for (int t = 0; t < NT; t++)
        g_xh[(size_t)n * (NT * C_IN) + t * C_IN + c] = __float2half_rn(v[t]);
}

__global__ void count_deg_kernel(const int* __restrict__ ei) {
    int e = blockIdx.x * blockDim.x + threadIdx.x;
    if (e >= N_EDGES) return;
    int dst = ei[N_EDGES + e];
    if ((unsigned)dst < (unsigned)N_NODES)
        atomicAdd(&g_deg[dst], 1);
}

__global__ void dinv_kernel() {
    int n = blockIdx.x * blockDim.x + threadIdx.x;
    if (n >= N_NODES) return;
    g_dinv[n] = rsqrtf((float)(g_deg[n] + 1));  // +1 self loop
}

// single-block exclusive scan of g_deg -> g_rowptr
__global__ void scan_kernel() {
    __shared__ int wsum[32];
    int tid = threadIdx.x;        // 1024 threads
    int lane = tid & 31, wid = tid >> 5;
    int running = 0;
    for (int base = 0; base < N_NODES; base += 1024) {
        int i = base + tid;
        int v = (i < N_NODES) ? g_deg[i] : 0;
        int x = v;
#pragma unroll
        for (int off = 1; off < 32; off <<= 1) {
            int y = __shfl_up_sync(0xffffffffu, x, off);
            if (lane >= off) x += y;
        }
        if (lane == 31) wsum[wid] = x;
        __syncthreads();
        if (wid == 0) {
            int s = wsum[lane];
#pragma unroll
            for (int off = 1; off < 32; off <<= 1) {
                int y = __shfl_up_sync(0xffffffffu, s, off);
                if (lane >= off) s += y;
            }
            wsum[lane] = s;
        }
        __syncthreads();
        int woff = (wid > 0) ? wsum[wid - 1] : 0;
        int incl = x + woff;
        if (i < N_NODES) g_rowptr[i] = running + incl - v;
        int total = wsum[31];
        __syncthreads();
        running += total;
    }
    if (tid == 0) g_rowptr[N_NODES] = running;
}

__global__ void fill_csr_kernel(const int* __restrict__ ei) {
    int e = blockIdx.x * blockDim.x + threadIdx.x;
    if (e >= N_EDGES) return;
    int src = ei[e];
    int dst = ei[N_EDGES + e];
    if ((unsigned)src >= (unsigned)N_NODES ||
        (unsigned)dst >= (unsigned)N_NODES) return;
    int pos = g_rowptr[dst] + atomicAdd(&g_cnt[dst], 1);
    g_src[pos]  = src;
    g_norm[pos] = g_dinv[src] * g_dinv[dst];
}

// ---------------- aggregation (all t at once), fp16 in/out -------------------
// agg32: warp per dst node; 4 passes of t-pairs packed in the lane dimension.
__global__ void __launch_bounds__(256) agg32_all_kernel(__half* __restrict__ out) {
    int w = (blockIdx.x * blockDim.x + threadIdx.x) >> 5;
    int lane = threadIdx.x & 31;
    if (w >= N_NODES) return;
    const __half2* X = (const __half2*)g_xh;
    float dv = g_dinv[w];
    float dv2 = dv * dv;
    float2 acc[4];
#pragma unroll
    for (int p = 0; p < 4; p++) {
        float2 f = __half22float2(X[(size_t)w * 128 + p * 32 + lane]);
        acc[p].x = dv2 * f.x; acc[p].y = dv2 * f.y;
    }
    int s = g_rowptr[w], e2 = g_rowptr[w + 1];
    for (int base = s; base < e2; base += 32) {
        int idx = base + lane;
        int sl = 0; float nl = 0.f;
        if (idx < e2) { sl = g_src[idx]; nl = g_norm[idx]; }
        int cnt = min(32, e2 - base);
        for (int j = 0; j < cnt; j++) {
            int src  = __shfl_sync(0xffffffffu, sl, j);
            float wt = __shfl_sync(0xffffffffu, nl, j);
#pragma unroll
            for (int p = 0; p < 4; p++) {
                float2 f = __half22float2(X[(size_t)src * 128 + p * 32 + lane]);
                acc[p].x = fmaf(wt, f.x, acc[p].x);
                acc[p].y = fmaf(wt, f.y, acc[p].y);
            }
        }
    }
    __half2* o2 = (__half2*)out;
#pragma unroll
    for (int p = 0; p < 4; p++) {
        int t = 2 * p + (lane >> 4);
        int cpair = lane & 15;
        o2[((size_t)t * N_NODES + w) * 16 + cpair] = __floats2half2_rn(acc[p].x, acc[p].y);
    }
}

// agg64: warp per dst node; lane -> half2 channel pair; loop all 8 t inside.
__global__ void __launch_bounds__(256) agg64_all_kernel(const __half* __restrict__ hin,
                                                        __half* __restrict__ out) {
    int w = (blockIdx.x * blockDim.x + threadIdx.x) >> 5;
    int lane = threadIdx.x & 31;
    if (w >= N_NODES) return;
    const __half2* H = (const __half2*)hin;
    float dv = g_dinv[w];
    float dv2 = dv * dv;
    float2 acc[NT];
#pragma unroll
    for (int t = 0; t < NT; t++) {
        float2 f = __half22float2(H[((size_t)t * N_NODES + w) * 32 + lane]);
        acc[t].x = dv2 * f.x; acc[t].y = dv2 * f.y;
    }
    int s = g_rowptr[w], e2 = g_rowptr[w + 1];
    for (int base = s; base < e2; base += 32) {
        int idx = base + lane;
        int sl = 0; float nl = 0.f;
        if (idx < e2) { sl = g_src[idx]; nl = g_norm[idx]; }
        int cnt = min(32, e2 - base);
        for (int j = 0; j < cnt; j++) {
            int src  = __shfl_sync(0xffffffffu, sl, j);
            float wt = __shfl_sync(0xffffffffu, nl, j);
#pragma unroll
            for (int t = 0; t < NT; t++) {
                float2 f = __half22float2(H[((size_t)t * N_NODES + src) * 32 + lane]);
                acc[t].x = fmaf(wt, f.x, acc[t].x);
                acc[t].y = fmaf(wt, f.y, acc[t].y);
            }
        }
    }
    __half2* o2 = (__half2*)out;
#pragma unroll
    for (int t = 0; t < NT; t++)
        o2[((size_t)t * N_NODES + w) * 32 + lane] = __floats2half2_rn(acc[t].x, acc[t].y);
}

// ---------------- HMMA GEMM: out = relu(A[M,K]h @ W[K,64]h + b) fp16 out -----
// Block = 128 rows x 64 cols, 8 warps: warp (wm 0..3, wn 0..1) -> 32 rows x 32 cols.
// mma.sync.m16n8k16 row.col f32 acc; fragments loaded straight from gmem.
__device__ __forceinline__ uint32_t pack_h2(__half a, __half b) {
    __half2 h = __halves2half2(a, b);
    return *(uint32_t*)&h;
}

template <int K>
__global__ void __launch_bounds__(256) hgemm_bias_relu_kernel(
    const __half* __restrict__ A, const __half* __restrict__ Wh,
    const float* __restrict__ bias, __half* __restrict__ out) {
    constexpr int KS = K / 16;
    int tid = threadIdx.x, lane = tid & 31, warp = tid >> 5;
    int wm = warp >> 1, wn = warp & 1;
    size_t row0 = (size_t)blockIdx.x * 128 + wm * 32;
    int col0 = wn * 32;
    int lq = lane >> 2, lr = lane & 3;   // lane/4, lane%4

    // preload B fragments: breg[ks][j][2]
    uint32_t breg[KS][4][2];
#pragma unroll
    for (int ks = 0; ks < KS; ks++)
#pragma unroll
        for (int j = 0; j < 4; j++) {
            int n  = col0 + j * 8 + lq;
            int kb = ks * 16 + lr * 2;
            breg[ks][j][0] = pack_h2(Wh[kb * 64 + n],       Wh[(kb + 1) * 64 + n]);
            breg[ks][j][1] = pack_h2(Wh[(kb + 8) * 64 + n], Wh[(kb + 9) * 64 + n]);
        }

    float acc[2][4][4];
#pragma unroll
    for (int mt = 0; mt < 2; mt++)
#pragma unroll
        for (int j = 0; j < 4; j++)
#pragma unroll
            for (int q = 0; q < 4; q++) acc[mt][j][q] = 0.f;

#pragma unroll
    for (int mt = 0; mt < 2; mt++) {
        const __half* Ab = A + (row0 + mt * 16) * K;
#pragma unroll
        for (int ks = 0; ks < KS; ks++) {
            int kc = ks * 16 + lr * 2;
            uint32_t a0 = *(const uint32_t*)(Ab + (size_t)lq * K + kc);
            uint32_t a1 = *(const uint32_t*)(Ab + (size_t)(lq + 8) * K + kc);
            uint32_t a2 = *(const uint32_t*)(Ab + (size_t)lq * K + kc + 8);
            uint32_t a3 = *(const uint32_t*)(Ab + (size_t)(lq + 8) * K + kc + 8);
#pragma unroll
            for (int j = 0; j < 4; j++) {
                asm volatile(
                    "mma.sync.aligned.m16n8k16.row.col.f32.f16.f16.f32 "
                    "{%0,%1,%2,%3}, {%4,%5,%6,%7}, {%8,%9}, {%0,%1,%2,%3};"
                    : "+f"(acc[mt][j][0]), "+f"(acc[mt][j][1]),
                      "+f"(acc[mt][j][2]), "+f"(acc[mt][j][3])
                    : "r"(a0), "r"(a1), "r"(a2), "r"(a3),
                      "r"(breg[ks][j][0]), "r"(breg[ks][j][1]));
            }
        }
    }

    // epilogue: bias + relu, fp16 store
#pragma unroll
    for (int mt = 0; mt < 2; mt++) {
#pragma unroll
        for (int j = 0; j < 4; j++) {
            int c = col0 + j * 8 + lr * 2;
            float bx = bias[c], by = bias[c + 1];
            size_t r0 = row0 + mt * 16 + lq;
            float ox = fmaxf(acc[mt][j][0] + bx, 0.f);
            float oy = fmaxf(acc[mt][j][1] + by, 0.f);
            *(__half2*)(out + r0 * 64 + c) = __floats2half2_rn(ox, oy);
            float oz = fmaxf(acc[mt][j][2] + bx, 0.f);
            float ow = fmaxf(acc[mt][j][3] + by, 0.f);
            *(__half2*)(out + (r0 + 8) * 64 + c) = __floats2half2_rn(oz, ow);
        }
    }
}

// ---------------- pooling (all t): out[b, 0:64, t] += max, [64:128] += mean --
__global__ void __launch_bounds__(256) pool_all_kernel(const __half* __restrict__ h,
                                                       float* __restrict__ out) {
    int b = blockIdx.x, t = blockIdx.y;
    int tid = threadIdx.x;
    int c = tid & 63, g = tid >> 6;  // 4 groups
    const __half* hp = h + (size_t)t * N_NODES * 64 + (size_t)b * NPG * 64;
    float mx = -1e30f, sm = 0.f;
    for (int i = g; i < NPG; i += 4) {
        float v = __half2float(hp[(size_t)i * 64 + c]);
        mx = fmaxf(mx, v);
        sm += v;
    }
    __shared__ float smx[4][64], ssm[4][64];
    smx[g][c] = mx; ssm[g][c] = sm;
    __syncthreads();
    if (tid < 64) {
        float m = fmaxf(fmaxf(smx[0][tid], smx[1][tid]),
                        fmaxf(smx[2][tid], smx[3][tid]));
        float s = ssm[0][tid] + ssm[1][tid] + ssm[2][tid] + ssm[3][tid];
        out[b * 1024 + tid * 8 + t]        += m;
        out[b * 1024 + (64 + tid) * 8 + t] += s * (1.f / (float)NPG);
    }
}

// ---------------- launch -----------------------------------------------------
extern "C" void kernel_launch(void* const* d_in, const int* in_sizes, int n_in,
                              void* d_out, int out_size) {
    const float* x  = (const float*)d_in[0];
    const int*   ei = (const int*)d_in[1];     // int32 [2, E]
    const float* W1 = (const float*)d_in[3];
    const float* b1 = (const float*)d_in[4];
    const float* W2 = (const float*)d_in[5];
    const float* b2 = (const float*)d_in[6];
    const float* W3 = (const float*)d_in[7];
    const float* b3 = (const float*)d_in[8];
    float* out = (float*)d_out;

    __half *agg, *h, *w1h, *w2h, *w3h;
    cudaGetSymbolAddress((void**)&agg, g_agg);
    cudaGetSymbolAddress((void**)&h,   g_h);
    cudaGetSymbolAddress((void**)&w1h, g_W1h);
    cudaGetSymbolAddress((void**)&w2h, g_W2h);
    cudaGetSymbolAddress((void**)&w3h, g_W3h);

    // setup
    zero_setup_kernel<<<(N_NODES + 255) / 256, 256>>>();
    zero_out_kernel<<<(NB * 128 * NT + 255) / 256, 256>>>(out, NB * 128 * NT);
    convert_w_kernel<<<(C_OUT * C_OUT + 255) / 256, 256>>>(W1, W2, W3);
    transpose_x_kernel<<<(N_NODES * C_IN + 255) / 256, 256>>>(x);
    count_deg_kernel<<<(N_EDGES + 255) / 256, 256>>>(ei);
    dinv_kernel<<<(N_NODES + 255) / 256, 256>>>();
    scan_kernel<<<1, 1024>>>();
    fill_csr_kernel<<<(N_EDGES + 255) / 256, 256>>>(ei);

    const int AGG_GRID  = N_NODES / 8;        // 8 warps/block, warp=node
    const int GEMM_GRID = M_ALL / 128;        // 3125
    dim3 pool_grid(NB, NT);

    // layer 1 (all t)
    agg32_all_kernel<<<AGG_GRID, 256>>>(agg);
    hgemm_bias_relu_kernel<32><<<GEMM_GRID, 256>>>(agg, w1h, b1, h);
    pool_all_kernel<<<pool_grid, 256>>>(h, out);
    // layer 2 (all t)
    agg64_all_kernel<<<AGG_GRID, 256>>>(h, agg);
    hgemm_bias_relu_kernel<64><<<GEMM_GRID, 256>>>(agg, w2h, b2, h);
    pool_all_kernel<<<pool_grid, 256>>>(h, out);
    // layer 3 (all t)
    agg64_all_kernel<<<AGG_GRID, 256>>>(h, agg);
    hgemm_bias_relu_kernel<64><<<GEMM_GRID, 256>>>(agg, w3h, b3, h);
    pool_all_kernel<<<pool_grid, 256>>>(h, out);
}

// round 7
// speedup vs baseline: 2.5621x; 1.0506x over previous
#include <cuda_runtime.h>
#include <cuda_fp16.h>
#include <math.h>
#include <stdint.h>

#define N_NODES 50000
#define N_EDGES 800000
#define NB      250
#define NT      8
#define C_IN    32
#define C_OUT   64
#define NPG     200   // nodes per graph (contiguous)
#define M_ALL   (NT * N_NODES)   // 400000 rows = n*8+t, divisible by 128

// ---------------- scratch (static device globals; no allocation) -------------
__device__ __half g_xh[(size_t)N_NODES * NT * C_IN];    // [n][t][c] fp16 (row 512B)
__device__ __half g_h[(size_t)N_NODES * NT * C_OUT];    // [n][t][c] fp16 (row 1024B)
__device__ __half g_agg[(size_t)N_NODES * NT * C_OUT];  // [n][t][c] fp16
__device__ __half g_W1h[C_IN * C_OUT];
__device__ __half g_W2h[C_OUT * C_OUT];
__device__ __half g_W3h[C_OUT * C_OUT];
__device__ int    g_deg[N_NODES];
__device__ int    g_cnt[N_NODES];
__device__ int    g_rowptr[N_NODES + 1];
__device__ float  g_dinv[N_NODES];
__device__ int    g_src[N_EDGES];
__device__ float  g_norm[N_EDGES];

// ---------------- fused setup: zero deg/cnt + convert W + transpose x --------
__global__ void setup_a_kernel(const float* __restrict__ x,
                               const float* __restrict__ W1,
                               const float* __restrict__ W2,
                               const float* __restrict__ W3) {
    int i = blockIdx.x * blockDim.x + threadIdx.x;
    if (i < N_NODES) { g_deg[i] = 0; g_cnt[i] = 0; }
    if (i < C_OUT * C_OUT) { g_W2h[i] = __float2half_rn(W2[i]);
                             g_W3h[i] = __float2half_rn(W3[i]); }
    if (i < C_IN * C_OUT)  g_W1h[i] = __float2half_rn(W1[i]);
    if (i >= N_NODES * C_IN) return;
    // transpose: x[N, C_IN, T] -> g_xh [n][t][c]
    int n = i / C_IN, c = i % C_IN;
    const float4* p = (const float4*)(x + (size_t)i * NT);
    float4 a = p[0], b4 = p[1];
    float v[8] = {a.x, a.y, a.z, a.w, b4.x, b4.y, b4.z, b4.w};
#pragma unroll
    for (int t = 0; t < NT; t++)
        g_xh[(size_t)n * (NT * C_IN) + t * C_IN + c] = __float2half_rn(v[t]);
}

__global__ void count_deg_kernel(const int* __restrict__ ei) {
    int e = blockIdx.x * blockDim.x + threadIdx.x;
    if (e >= N_EDGES) return;
    int dst = ei[N_EDGES + e];
    if ((unsigned)dst < (unsigned)N_NODES)
        atomicAdd(&g_deg[dst], 1);
}

__global__ void dinv_kernel() {
    int n = blockIdx.x * blockDim.x + threadIdx.x;
    if (n >= N_NODES) return;
    g_dinv[n] = rsqrtf((float)(g_deg[n] + 1));  // +1 self loop
}

// single-block exclusive scan of g_deg -> g_rowptr
__global__ void scan_kernel() {
    __shared__ int wsum[32];
    int tid = threadIdx.x;        // 1024 threads
    int lane = tid & 31, wid = tid >> 5;
    int running = 0;
    for (int base = 0; base < N_NODES; base += 1024) {
        int i = base + tid;
        int v = (i < N_NODES) ? g_deg[i] : 0;
        int x = v;
#pragma unroll
        for (int off = 1; off < 32; off <<= 1) {
            int y = __shfl_up_sync(0xffffffffu, x, off);
            if (lane >= off) x += y;
        }
        if (lane == 31) wsum[wid] = x;
        __syncthreads();
        if (wid == 0) {
            int s = wsum[lane];
#pragma unroll
            for (int off = 1; off < 32; off <<= 1) {
                int y = __shfl_up_sync(0xffffffffu, s, off);
                if (lane >= off) s += y;
            }
            wsum[lane] = s;
        }
        __syncthreads();
        int woff = (wid > 0) ? wsum[wid - 1] : 0;
        int incl = x + woff;
        if (i < N_NODES) g_rowptr[i] = running + incl - v;
        int total = wsum[31];
        __syncthreads();
        running += total;
    }
    if (tid == 0) g_rowptr[N_NODES] = running;
}

__global__ void fill_csr_kernel(const int* __restrict__ ei) {
    int e = blockIdx.x * blockDim.x + threadIdx.x;
    if (e >= N_EDGES) return;
    int src = ei[e];
    int dst = ei[N_EDGES + e];
    if ((unsigned)src >= (unsigned)N_NODES ||
        (unsigned)dst >= (unsigned)N_NODES) return;
    int pos = g_rowptr[dst] + atomicAdd(&g_cnt[dst], 1);
    g_src[pos]  = src;
    g_norm[pos] = g_dinv[src] * g_dinv[dst];
}

// ---------------- aggregation: elementwise over node rows --------------------
__device__ __forceinline__ float2 u2f(uint32_t u) {
    __half2 h = *(__half2*)&u;
    return __half22float2(h);
}
__device__ __forceinline__ uint32_t f2u(float a, float b) {
    __half2 h = __floats2half2_rn(a, b);
    return *(uint32_t*)&h;
}

// agg32: row = 512B = 32 uint4; lane owns one uint4 (4 half2 -> 8 floats acc)
__global__ void __launch_bounds__(256) agg32_all_kernel(uint4* __restrict__ out) {
    int w = (blockIdx.x * blockDim.x + threadIdx.x) >> 5;
    int lane = threadIdx.x & 31;
    if (w >= N_NODES) return;
    const uint4* X4 = (const uint4*)g_xh;
    float dv = g_dinv[w];
    float dv2 = dv * dv;
    uint4 v = __ldg(&X4[(size_t)w * 32 + lane]);
    float2 a0 = u2f(v.x), a1 = u2f(v.y), a2 = u2f(v.z), a3 = u2f(v.w);
    a0.x *= dv2; a0.y *= dv2; a1.x *= dv2; a1.y *= dv2;
    a2.x *= dv2; a2.y *= dv2; a3.x *= dv2; a3.y *= dv2;
    int s = g_rowptr[w], e2 = g_rowptr[w + 1];
    for (int base = s; base < e2; base += 32) {
        int idx = base + lane;
        int sl = 0; float nl = 0.f;
        if (idx < e2) { sl = g_src[idx]; nl = g_norm[idx]; }
        int cnt = min(32, e2 - base);
        for (int j = 0; j < cnt; j++) {
            int src  = __shfl_sync(0xffffffffu, sl, j);
            float wt = __shfl_sync(0xffffffffu, nl, j);
            uint4 u = __ldg(&X4[(size_t)src * 32 + lane]);
            float2 f0 = u2f(u.x), f1 = u2f(u.y), f2 = u2f(u.z), f3 = u2f(u.w);
            a0.x = fmaf(wt, f0.x, a0.x); a0.y = fmaf(wt, f0.y, a0.y);
            a1.x = fmaf(wt, f1.x, a1.x); a1.y = fmaf(wt, f1.y, a1.y);
            a2.x = fmaf(wt, f2.x, a2.x); a2.y = fmaf(wt, f2.y, a2.y);
            a3.x = fmaf(wt, f3.x, a3.x); a3.y = fmaf(wt, f3.y, a3.y);
        }
    }
    uint4 o;
    o.x = f2u(a0.x, a0.y); o.y = f2u(a1.x, a1.y);
    o.z = f2u(a2.x, a2.y); o.w = f2u(a3.x, a3.y);
    out[(size_t)w * 32 + lane] = o;
}

// agg64: row = 1024B = 64 uint4; lane owns two uint4 (16 floats acc)
__global__ void __launch_bounds__(256) agg64_all_kernel(const uint4* __restrict__ in,
                                                        uint4* __restrict__ out) {
    int w = (blockIdx.x * blockDim.x + threadIdx.x) >> 5;
    int lane = threadIdx.x & 31;
    if (w >= N_NODES) return;
    float dv = g_dinv[w];
    float dv2 = dv * dv;
    float2 acc[8];
    {
        uint4 v0 = __ldg(&in[(size_t)w * 64 + lane]);
        uint4 v1 = __ldg(&in[(size_t)w * 64 + 32 + lane]);
        uint32_t u[8] = {v0.x, v0.y, v0.z, v0.w, v1.x, v1.y, v1.z, v1.w};
#pragma unroll
        for (int k = 0; k < 8; k++) {
            float2 f = u2f(u[k]);
            acc[k].x = dv2 * f.x; acc[k].y = dv2 * f.y;
        }
    }
    int s = g_rowptr[w], e2 = g_rowptr[w + 1];
    for (int base = s; base < e2; base += 32) {
        int idx = base + lane;
        int sl = 0; float nl = 0.f;
        if (idx < e2) { sl = g_src[idx]; nl = g_norm[idx]; }
        int cnt = min(32, e2 - base);
        for (int j = 0; j < cnt; j++) {
            int src  = __shfl_sync(0xffffffffu, sl, j);
            float wt = __shfl_sync(0xffffffffu, nl, j);
            uint4 v0 = __ldg(&in[(size_t)src * 64 + lane]);
            uint4 v1 = __ldg(&in[(size_t)src * 64 + 32 + lane]);
            uint32_t u[8] = {v0.x, v0.y, v0.z, v0.w, v1.x, v1.y, v1.z, v1.w};
#pragma unroll
            for (int k = 0; k < 8; k++) {
                float2 f = u2f(u[k]);
                acc[k].x = fmaf(wt, f.x, acc[k].x);
                acc[k].y = fmaf(wt, f.y, acc[k].y);
            }
        }
    }
    uint4 o0, o1;
    o0.x = f2u(acc[0].x, acc[0].y); o0.y = f2u(acc[1].x, acc[1].y);
    o0.z = f2u(acc[2].x, acc[2].y); o0.w = f2u(acc[3].x, acc[3].y);
    o1.x = f2u(acc[4].x, acc[4].y); o1.y = f2u(acc[5].x, acc[5].y);
    o1.z = f2u(acc[6].x, acc[6].y); o1.w = f2u(acc[7].x, acc[7].y);
    out[(size_t)w * 64 + lane] = o0;
    out[(size_t)w * 64 + 32 + lane] = o1;
}

// ---------------- HMMA GEMM: out = relu(A[M,K]h @ W[K,64]h + b) fp16 out -----
// Rows are flat r = n*8+t (layout [n][t][c]). Block = 128 rows x 64 cols.
__device__ __forceinline__ uint32_t pack_h2(__half a, __half b) {
    __half2 h = __halves2half2(a, b);
    return *(uint32_t*)&h;
}

template <int K>
__global__ void __launch_bounds__(256) hgemm_bias_relu_kernel(
    const __half* __restrict__ A, const __half* __restrict__ Wh,
    const float* __restrict__ bias, __half* __restrict__ out) {
    constexpr int KS = K / 16;
    int tid = threadIdx.x, lane = tid & 31, warp = tid >> 5;
    int wm = warp >> 1, wn = warp & 1;
    size_t row0 = (size_t)blockIdx.x * 128 + wm * 32;
    int col0 = wn * 32;
    int lq = lane >> 2, lr = lane & 3;   // lane/4, lane%4

    // preload B fragments
    uint32_t breg[KS][4][2];
#pragma unroll
    for (int ks = 0; ks < KS; ks++)
#pragma unroll
        for (int j = 0; j < 4; j++) {
            int n  = col0 + j * 8 + lq;
            int kb = ks * 16 + lr * 2;
            breg[ks][j][0] = pack_h2(Wh[kb * 64 + n],       Wh[(kb + 1) * 64 + n]);
            breg[ks][j][1] = pack_h2(Wh[(kb + 8) * 64 + n], Wh[(kb + 9) * 64 + n]);
        }

    float acc[2][4][4];
#pragma unroll
    for (int mt = 0; mt < 2; mt++)
#pragma unroll
        for (int j = 0; j < 4; j++)
#pragma unroll
            for (int q = 0; q < 4; q++) acc[mt][j][q] = 0.f;

#pragma unroll
    for (int mt = 0; mt < 2; mt++) {
        const __half* Ab = A + (row0 + mt * 16) * K;
#pragma unroll
        for (int ks = 0; ks < KS; ks++) {
            int kc = ks * 16 + lr * 2;
            uint32_t a0 = *(const uint32_t*)(Ab + (size_t)lq * K + kc);
            uint32_t a1 = *(const uint32_t*)(Ab + (size_t)(lq + 8) * K + kc);
            uint32_t a2 = *(const uint32_t*)(Ab + (size_t)lq * K + kc + 8);
            uint32_t a3 = *(const uint32_t*)(Ab + (size_t)(lq + 8) * K + kc + 8);
#pragma unroll
            for (int j = 0; j < 4; j++) {
                asm volatile(
                    "mma.sync.aligned.m16n8k16.row.col.f32.f16.f16.f32 "
                    "{%0,%1,%2,%3}, {%4,%5,%6,%7}, {%8,%9}, {%0,%1,%2,%3};"
                    : "+f"(acc[mt][j][0]), "+f"(acc[mt][j][1]),
                      "+f"(acc[mt][j][2]), "+f"(acc[mt][j][3])
                    : "r"(a0), "r"(a1), "r"(a2), "r"(a3),
                      "r"(breg[ks][j][0]), "r"(breg[ks][j][1]));
            }
        }
    }

    // epilogue: bias + relu, fp16 store
#pragma unroll
    for (int mt = 0; mt < 2; mt++) {
#pragma unroll
        for (int j = 0; j < 4; j++) {
            int c = col0 + j * 8 + lr * 2;
            float bx = bias[c], by = bias[c + 1];
            size_t r0 = row0 + mt * 16 + lq;
            float ox = fmaxf(acc[mt][j][0] + bx, 0.f);
            float oy = fmaxf(acc[mt][j][1] + by, 0.f);
            *(__half2*)(out + r0 * 64 + c) = __floats2half2_rn(ox, oy);
            float oz = fmaxf(acc[mt][j][2] + bx, 0.f);
            float ow = fmaxf(acc[mt][j][3] + by, 0.f);
            *(__half2*)(out + (r0 + 8) * 64 + c) = __floats2half2_rn(oz, ow);
        }
    }
}

// ---------------- pooling: out[b, c, t] (max) and [b, 64+c, t] (mean) --------
// h layout [n][t][c]. FIRST: store; else accumulate.
template <bool FIRST>
__global__ void __launch_bounds__(256) pool_all_kernel(const __half* __restrict__ h,
                                                       float* __restrict__ out) {
    int b = blockIdx.x, t = blockIdx.y;
    int tid = threadIdx.x;
    int c = tid & 63, g = tid >> 6;  // 4 groups
    const __half* hp = h + ((size_t)b * NPG * 8 + t) * 64 + c;
    float mx = -1e30f, sm = 0.f;
    for (int i = g; i < NPG; i += 4) {
        float v = __half2float(hp[(size_t)i * 512]);
        mx = fmaxf(mx, v);
        sm += v;
    }
    __shared__ float smx[4][64], ssm[4][64];
    smx[g][c] = mx; ssm[g][c] = sm;
    __syncthreads();
    if (tid < 64) {
        float m = fmaxf(fmaxf(smx[0][tid], smx[1][tid]),
                        fmaxf(smx[2][tid], smx[3][tid]));
        float s = (ssm[0][tid] + ssm[1][tid] + ssm[2][tid] + ssm[3][tid])
                  * (1.f / (float)NPG);
        if (FIRST) {
            out[b * 1024 + tid * 8 + t]        = m;
            out[b * 1024 + (64 + tid) * 8 + t] = s;
        } else {
            out[b * 1024 + tid * 8 + t]        += m;
            out[b * 1024 + (64 + tid) * 8 + t] += s;
        }
    }
}

// ---------------- launch -----------------------------------------------------
extern "C" void kernel_launch(void* const* d_in, const int* in_sizes, int n_in,
                              void* d_out, int out_size) {
    const float* x  = (const float*)d_in[0];
    const int*   ei = (const int*)d_in[1];     // int32 [2, E]
    const float* W1 = (const float*)d_in[3];
    const float* b1 = (const float*)d_in[4];
    const float* W2 = (const float*)d_in[5];
    const float* b2 = (const float*)d_in[6];
    const float* W3 = (const float*)d_in[7];
    const float* b3 = (const float*)d_in[8];
    float* out = (float*)d_out;

    __half *agg, *h, *w1h, *w2h, *w3h;
    cudaGetSymbolAddress((void**)&agg, g_agg);
    cudaGetSymbolAddress((void**)&h,   g_h);
    cudaGetSymbolAddress((void**)&w1h, g_W1h);
    cudaGetSymbolAddress((void**)&w2h, g_W2h);
    cudaGetSymbolAddress((void**)&w3h, g_W3h);

    // setup: 5 launches, so ncu -s 5 profiles agg32_all (launch index 5)
    setup_a_kernel<<<(N_NODES * C_IN + 255) / 256, 256>>>(x, W1, W2, W3);
    count_deg_kernel<<<(N_EDGES + 255) / 256, 256>>>(ei);
    dinv_kernel<<<(N_NODES + 255) / 256, 256>>>();
    scan_kernel<<<1, 1024>>>();
    fill_csr_kernel<<<(N_EDGES + 255) / 256, 256>>>(ei);

    const int AGG_GRID  = N_NODES / 8;        // 8 warps/block, warp=node
    const int GEMM_GRID = M_ALL / 128;        // 3125
    dim3 pool_grid(NB, NT);

    // layer 1
    agg32_all_kernel<<<AGG_GRID, 256>>>((uint4*)agg);
    hgemm_bias_relu_kernel<32><<<GEMM_GRID, 256>>>(agg, w1h, b1, h);
    pool_all_kernel<true><<<pool_grid, 256>>>(h, out);
    // layer 2
    agg64_all_kernel<<<AGG_GRID, 256>>>((const uint4*)h, (uint4*)agg);
    hgemm_bias_relu_kernel<64><<<GEMM_GRID, 256>>>(agg, w2h, b2, h);
    pool_all_kernel<false><<<pool_grid, 256>>>(h, out);
    // layer 3
    agg64_all_kernel<<<AGG_GRID, 256>>>((const uint4*)h, (uint4*)agg);
    hgemm_bias_relu_kernel<64><<<GEMM_GRID, 256>>>(agg, w3h, b3, h);
    pool_all_kernel<false><<<pool_grid, 256>>>(h, out);
}